// round 5
// baseline (speedup 1.0000x reference)
#include <cuda_runtime.h>
#include <math.h>

#define NPTS   8192
#define NPARTS 2
#define CHUNK  2048
#define TPB    128

// Scratch (no allocs allowed): transforms (top 3 rows) + per-point nearest distances.
__device__ float g_xf[2][12];            // [part][r*4+c], part0 = base, part1 = rel@base
__device__ float g_dist[2][2][NPTS];     // [part][dir][point]

// ---------------------------------------------------------------------------
// Setup: quat->rot, base transform, revolute transform, T = rel @ base.
// Writes transforms into d_out (f32) and g_xf (f32, rows 0..2).
// Output layout (35 floats): [0]=all, [1]=base_obj, [2]=child_obj,
//                            [3..18]=base_transform, [19..34]=rel_transform
// ---------------------------------------------------------------------------
__global__ void k_setup(const float* __restrict__ xyz, const float* __restrict__ rpy,
                        const float* __restrict__ quat, const float* __restrict__ bt,
                        const float* __restrict__ theta, float* __restrict__ out)
{
    if (threadIdx.x != 0) return;

    // --- base transform from quaternion (normalized) + translation ---
    float qa = quat[0], qb = quat[1], qc = quat[2], qd = quat[3];
    float qn = sqrtf(qa*qa + qb*qb + qc*qc + qd*qd);
    qa /= qn; qb /= qn; qc /= qn; qd /= qn;

    float B[16];
    B[0]  = 1.f - 2.f*qc*qc - 2.f*qd*qd;  B[1]  = 2.f*qb*qc - 2.f*qa*qd;        B[2]  = 2.f*qa*qc + 2.f*qb*qd;        B[3]  = bt[0];
    B[4]  = 2.f*qb*qc + 2.f*qa*qd;        B[5]  = 1.f - 2.f*qb*qb - 2.f*qd*qd;  B[6]  = 2.f*qc*qd - 2.f*qa*qb;        B[7]  = bt[1];
    B[8]  = 2.f*qb*qd - 2.f*qa*qc;        B[9]  = 2.f*qa*qb + 2.f*qc*qd;        B[10] = 1.f - 2.f*qb*qb - 2.f*qc*qc;  B[11] = bt[2];
    B[12] = 0.f; B[13] = 0.f; B[14] = 0.f; B[15] = 1.f;

    // --- revolute (screw) transform; axis NOT normalized (matches reference) ---
    float ax = xyz[0], ay = xyz[1], az = xyz[2];
    float u  = rpy[0], v  = rpy[1], w  = rpy[2];
    float th = theta[0];
    float co = cosf(th), si = sinf(th), omc = 1.f - co;

    float R[16];
    R[0]  = u*u + (v*v + w*w)*co;   R[1]  = u*v*omc - w*si;          R[2]  = u*w*omc + v*si;
    R[3]  = (ax*(v*v + w*w) - u*(ay*v + az*w))*omc + (ay*w - az*v)*si;
    R[4]  = u*v*omc + w*si;         R[5]  = v*v + (u*u + w*w)*co;    R[6]  = v*w*omc - u*si;
    R[7]  = (ay*(u*u + w*w) - v*(ax*u + az*w))*omc + (az*u - ax*w)*si;
    R[8]  = u*w*omc - v*si;         R[9]  = v*w*omc + u*si;          R[10] = w*w + (u*u + v*v)*co;
    R[11] = (az*(u*u + v*v) - w*(ax*u + ay*v))*omc + (ax*v - ay*u)*si;
    R[12] = 0.f; R[13] = 0.f; R[14] = 0.f; R[15] = 1.f;

    // --- T = R @ B (4x4) ---
    float T[16];
    #pragma unroll
    for (int r = 0; r < 4; r++)
        #pragma unroll
        for (int c = 0; c < 4; c++) {
            float s = 0.f;
            #pragma unroll
            for (int k = 0; k < 4; k++) s += R[r*4 + k] * B[k*4 + c];
            T[r*4 + c] = s;
        }

    #pragma unroll
    for (int i = 0; i < 12; i++) { g_xf[0][i] = B[i]; g_xf[1][i] = T[i]; }

    #pragma unroll
    for (int i = 0; i < 16; i++) { out[3 + i] = B[i]; out[19 + i] = R[i]; }
}

// ---------------------------------------------------------------------------
// Chamfer: grid (NPTS/TPB, dir, part). One query point per thread; db tiled
// through smem as float4(x,y,z,|y|^2). dir0: query=transformed cad, db=cam.
// dir1: query=cam, db=transformed cad (transform applied while staging).
// min_j(|q|^2+|y|^2-2q.y) = |q|^2 + min_j(|y_j|^2 - 2 q.y_j)  (exact hoist)
// ---------------------------------------------------------------------------
__global__ void k_chamfer(const float* __restrict__ cam, const float* __restrict__ cad)
{
    const int part = blockIdx.z;
    const int dir  = blockIdx.y;
    const int q    = blockIdx.x * TPB + threadIdx.x;

    const float* camP = cam + part * NPTS * 3;
    const float* cadP = cad + part * NPTS * 3;

    float t0 = g_xf[part][0],  t1 = g_xf[part][1],  t2  = g_xf[part][2],  t3  = g_xf[part][3];
    float t4 = g_xf[part][4],  t5 = g_xf[part][5],  t6  = g_xf[part][6],  t7  = g_xf[part][7];
    float t8 = g_xf[part][8],  t9 = g_xf[part][9],  t10 = g_xf[part][10], t11 = g_xf[part][11];

    // query point
    float qx, qy, qz;
    {
        const float* src = (dir == 0) ? cadP : camP;
        float x = src[3*q], y = src[3*q + 1], z = src[3*q + 2];
        if (dir == 0) {
            qx = t0*x + t1*y + t2*z  + t3;
            qy = t4*x + t5*y + t6*z  + t7;
            qz = t8*x + t9*y + t10*z + t11;
        } else { qx = x; qy = y; qz = z; }
    }
    const float qnorm = qx*qx + qy*qy + qz*qz;

    // Two independent min accumulators: breaks the FMNMX dependency chain.
    float m0 = 3.4e38f, m1 = 3.4e38f;
    __shared__ float4 sm[CHUNK];

    for (int ch = 0; ch < NPTS / CHUNK; ch++) {
        __syncthreads();
        for (int j = threadIdx.x; j < CHUNK; j += TPB) {
            int gj = ch * CHUNK + j;
            float x, y, z;
            if (dir == 0) {
                x = camP[3*gj]; y = camP[3*gj + 1]; z = camP[3*gj + 2];
            } else {
                float cx = cadP[3*gj], cy = cadP[3*gj + 1], cz = cadP[3*gj + 2];
                x = t0*cx + t1*cy + t2*cz  + t3;
                y = t4*cx + t5*cy + t6*cz  + t7;
                z = t8*cx + t9*cy + t10*cz + t11;
            }
            sm[j] = make_float4(x, y, z, x*x + y*y + z*z);
        }
        __syncthreads();

        #pragma unroll 16
        for (int j = 0; j < CHUNK; j += 2) {
            float4 p0 = sm[j];
            float4 p1 = sm[j + 1];
            float dot0 = fmaf(qx, p0.x, fmaf(qy, p0.y, qz * p0.z));
            float dot1 = fmaf(qx, p1.x, fmaf(qy, p1.y, qz * p1.z));
            m0 = fminf(m0, fmaf(-2.f, dot0, p0.w));
            m1 = fminf(m1, fmaf(-2.f, dot1, p1.w));
        }
    }

    float d2 = fmaxf(qnorm + fminf(m0, m1), 0.f);
    g_dist[part][dir][q] = sqrtf(d2);
}

// ---------------------------------------------------------------------------
// Final reduction: per-part objective = mean(dist dir0) + mean(dist dir1),
// fp64 accumulation internally; stores float32 to out[0..2].
// ---------------------------------------------------------------------------
__global__ void k_reduce(const float* __restrict__ pw, float* __restrict__ out)
{
    __shared__ double s0[256], s1[256];
    const int tid = threadIdx.x;
    const float* d0 = &g_dist[0][0][0];
    const float* d1 = &g_dist[1][0][0];

    double a0 = 0.0, a1 = 0.0;
    for (int i = tid; i < 2 * NPTS; i += 256) {
        a0 += (double)d0[i];
        a1 += (double)d1[i];
    }
    s0[tid] = a0; s1[tid] = a1;
    __syncthreads();
    for (int s = 128; s > 0; s >>= 1) {
        if (tid < s) { s0[tid] += s0[tid + s]; s1[tid] += s1[tid + s]; }
        __syncthreads();
    }
    if (tid == 0) {
        double obj0 = s0[0] / (double)NPTS;   // base part
        double obj1 = s1[0] / (double)NPTS;   // child part
        out[1] = (float)obj0;
        out[2] = (float)obj1;
        out[0] = (float)(((double)pw[0] * obj0 + (double)pw[1] * obj1) / (double)NPARTS);
    }
}

// ---------------------------------------------------------------------------
extern "C" void kernel_launch(void* const* d_in, const int* in_sizes, int n_in,
                              void* d_out, int out_size)
{
    const float* cam  = (const float*)d_in[0];  // camera_pts [2,8192,3]
    const float* cad  = (const float*)d_in[1];  // cad_pts    [2,8192,3]
    const float* xyz  = (const float*)d_in[2];  // [1,3]
    const float* rpy  = (const float*)d_in[3];  // [1,3]
    const float* pw   = (const float*)d_in[4];  // [2]
    const float* quat = (const float*)d_in[5];  // [4]
    const float* bt   = (const float*)d_in[6];  // [3,1]
    const float* th   = (const float*)d_in[7];  // [1]
    float* out = (float*)d_out;

    k_setup<<<1, 32>>>(xyz, rpy, quat, bt, th, out);

    dim3 grid(NPTS / TPB, 2, 2);   // (query blocks, dir, part) = 256 blocks
    k_chamfer<<<grid, TPB>>>(cam, cad);

    k_reduce<<<1, 256>>>(pw, out);
}

// round 6
// speedup vs baseline: 1.3920x; 1.3920x over previous
#include <cuda_runtime.h>
#include <math.h>

#define NPTS   8192
#define CHUNK  2048
#define TPB    256
#define NBLK   128      // grid (32, 2, 2)

// Scratch (no allocs allowed)
__device__ double       g_bsum[NBLK];
__device__ unsigned int g_count;   // zero-init; last block resets -> replay-safe

__device__ __forceinline__ unsigned long long pack2(float lo, float hi) {
    unsigned long long r;
    asm("mov.b64 %0, {%1, %2};" : "=l"(r)
        : "r"(__float_as_uint(lo)), "r"(__float_as_uint(hi)));
    return r;
}
__device__ __forceinline__ unsigned long long fma2(unsigned long long a,
                                                   unsigned long long b,
                                                   unsigned long long c) {
    unsigned long long d;
    asm("fma.rn.f32x2 %0, %1, %2, %3;" : "=l"(d) : "l"(a), "l"(b), "l"(c));
    return d;
}

// ---------------------------------------------------------------------------
// Fused: transforms + chamfer + reduction in ONE launch.
// grid (32,2,2): blockIdx.x = query tile, .y = direction, .z = part.
// dir0: query = transformed cad, db = cam.  dir1: query = cam, db = transformed cad.
// min_j |q-y_j|^2 = |q|^2 + min_j(|y_j|^2 - 2 q.y_j); -2 folded into staged db coords.
// Inner loop: 2 db points per iter via packed f32x2 FMA.
// ---------------------------------------------------------------------------
__global__ void __launch_bounds__(TPB, 1)
k_fused(const float* __restrict__ cam, const float* __restrict__ cad,
        const float* __restrict__ xyz, const float* __restrict__ rpy,
        const float* __restrict__ quat, const float* __restrict__ bt,
        const float* __restrict__ theta, const float* __restrict__ pw,
        float* __restrict__ out)
{
    __shared__ float4 sxy[CHUNK / 2];   // (-2x0,-2x1,-2y0,-2y1)
    __shared__ float4 szw[CHUNK / 2];   // (-2z0,-2z1,  w0,  w1)
    __shared__ float  sxf[12];
    __shared__ double sred[TPB];
    __shared__ int    s_last;

    const int part = blockIdx.z;
    const int dir  = blockIdx.y;
    const int tid  = threadIdx.x;
    const int q    = blockIdx.x * TPB + tid;

    // --- per-block transform setup (thread 0) ---
    if (tid == 0) {
        float qa = quat[0], qb = quat[1], qc = quat[2], qd = quat[3];
        float qn = sqrtf(qa*qa + qb*qb + qc*qc + qd*qd);
        qa /= qn; qb /= qn; qc /= qn; qd /= qn;

        float B[16];
        B[0]  = 1.f - 2.f*qc*qc - 2.f*qd*qd;  B[1]  = 2.f*qb*qc - 2.f*qa*qd;        B[2]  = 2.f*qa*qc + 2.f*qb*qd;        B[3]  = bt[0];
        B[4]  = 2.f*qb*qc + 2.f*qa*qd;        B[5]  = 1.f - 2.f*qb*qb - 2.f*qd*qd;  B[6]  = 2.f*qc*qd - 2.f*qa*qb;        B[7]  = bt[1];
        B[8]  = 2.f*qb*qd - 2.f*qa*qc;        B[9]  = 2.f*qa*qb + 2.f*qc*qd;        B[10] = 1.f - 2.f*qb*qb - 2.f*qc*qc;  B[11] = bt[2];
        B[12] = 0.f; B[13] = 0.f; B[14] = 0.f; B[15] = 1.f;

        float ax = xyz[0], ay = xyz[1], az = xyz[2];
        float u  = rpy[0], v  = rpy[1], w  = rpy[2];
        float th = theta[0];
        float co = cosf(th), si = sinf(th), omc = 1.f - co;

        float R[16];
        R[0]  = u*u + (v*v + w*w)*co;   R[1]  = u*v*omc - w*si;          R[2]  = u*w*omc + v*si;
        R[3]  = (ax*(v*v + w*w) - u*(ay*v + az*w))*omc + (ay*w - az*v)*si;
        R[4]  = u*v*omc + w*si;         R[5]  = v*v + (u*u + w*w)*co;    R[6]  = v*w*omc - u*si;
        R[7]  = (ay*(u*u + w*w) - v*(ax*u + az*w))*omc + (az*u - ax*w)*si;
        R[8]  = u*w*omc - v*si;         R[9]  = v*w*omc + u*si;          R[10] = w*w + (u*u + v*v)*co;
        R[11] = (az*(u*u + v*v) - w*(ax*u + ay*v))*omc + (ax*v - ay*u)*si;
        R[12] = 0.f; R[13] = 0.f; R[14] = 0.f; R[15] = 1.f;

        float T[16];
        #pragma unroll
        for (int r = 0; r < 4; r++)
            #pragma unroll
            for (int c = 0; c < 4; c++) {
                float s = 0.f;
                #pragma unroll
                for (int k = 0; k < 4; k++) s += R[r*4 + k] * B[k*4 + c];
                T[r*4 + c] = s;
            }

        const float* X = (part == 0) ? B : T;
        #pragma unroll
        for (int i = 0; i < 12; i++) sxf[i] = X[i];

        if (blockIdx.x == 0 && dir == 0 && part == 0) {
            // out layout: [0]=all, [1]=base_obj, [2]=child_obj, [3..18]=base_T, [19..34]=rel_T
            #pragma unroll
            for (int i = 0; i < 16; i++) { out[3 + i] = B[i]; out[19 + i] = R[i]; }
        }
    }
    __syncthreads();

    const float t0 = sxf[0], t1 = sxf[1], t2  = sxf[2],  t3  = sxf[3];
    const float t4 = sxf[4], t5 = sxf[5], t6  = sxf[6],  t7  = sxf[7];
    const float t8 = sxf[8], t9 = sxf[9], t10 = sxf[10], t11 = sxf[11];

    const float* camP = cam + part * NPTS * 3;
    const float* cadP = cad + part * NPTS * 3;

    // query point
    float qx, qy, qz;
    {
        const float* src = (dir == 0) ? cadP : camP;
        float x = src[3*q], y = src[3*q + 1], z = src[3*q + 2];
        if (dir == 0) {
            qx = t0*x + t1*y + t2*z  + t3;
            qy = t4*x + t5*y + t6*z  + t7;
            qz = t8*x + t9*y + t10*z + t11;
        } else { qx = x; qy = y; qz = z; }
    }
    const float qnorm = qx*qx + qy*qy + qz*qz;
    const unsigned long long qx2 = pack2(qx, qx);
    const unsigned long long qy2 = pack2(qy, qy);
    const unsigned long long qz2 = pack2(qz, qz);

    float m0 = 3.4e38f, m1 = 3.4e38f;

    for (int ch = 0; ch < NPTS / CHUNK; ch++) {
        __syncthreads();
        // stage 2 db points per slot, -2 pre-folded into coords
        for (int jp = tid; jp < CHUNK / 2; jp += TPB) {
            int g0 = ch * CHUNK + 2 * jp;
            float x0, y0, z0, x1, y1, z1;
            if (dir == 0) {
                x0 = camP[3*g0];     y0 = camP[3*g0 + 1]; z0 = camP[3*g0 + 2];
                x1 = camP[3*g0 + 3]; y1 = camP[3*g0 + 4]; z1 = camP[3*g0 + 5];
            } else {
                float a0 = cadP[3*g0],     b0 = cadP[3*g0 + 1], c0 = cadP[3*g0 + 2];
                float a1 = cadP[3*g0 + 3], b1 = cadP[3*g0 + 4], c1 = cadP[3*g0 + 5];
                x0 = t0*a0 + t1*b0 + t2*c0  + t3;   x1 = t0*a1 + t1*b1 + t2*c1  + t3;
                y0 = t4*a0 + t5*b0 + t6*c0  + t7;   y1 = t4*a1 + t5*b1 + t6*c1  + t7;
                z0 = t8*a0 + t9*b0 + t10*c0 + t11;  z1 = t8*a1 + t9*b1 + t10*c1 + t11;
            }
            float w0 = x0*x0 + y0*y0 + z0*z0;
            float w1 = x1*x1 + y1*y1 + z1*z1;
            sxy[jp] = make_float4(-2.f*x0, -2.f*x1, -2.f*y0, -2.f*y1);
            szw[jp] = make_float4(-2.f*z0, -2.f*z1,  w0,      w1);
        }
        __syncthreads();

        #pragma unroll 8
        for (int i = 0; i < CHUNK / 2; i++) {
            ulonglong2 a = *reinterpret_cast<const ulonglong2*>(&sxy[i]); // a.x=xp, a.y=yp
            ulonglong2 b = *reinterpret_cast<const ulonglong2*>(&szw[i]); // b.x=zp, b.y=wp
            unsigned long long t = fma2(qz2, b.x, b.y);   // w - 2 qz*z
            t = fma2(qy2, a.y, t);
            t = fma2(qx2, a.x, t);                        // w - 2 q.y  (both points)
            unsigned int lo, hi;
            asm("mov.b64 {%0, %1}, %2;" : "=r"(lo), "=r"(hi) : "l"(t));
            m0 = fminf(m0, __uint_as_float(lo));
            m1 = fminf(m1, __uint_as_float(hi));
        }
    }

    const float d = sqrtf(fmaxf(qnorm + fminf(m0, m1), 0.f));

    // --- deterministic block reduction (fp64) ---
    sred[tid] = (double)d;
    __syncthreads();
    for (int s = TPB / 2; s > 0; s >>= 1) {
        if (tid < s) sred[tid] += sred[tid + s];
        __syncthreads();
    }

    const int blin = blockIdx.x + gridDim.x * (dir + 2 * part); // 0..127; part = blin/64
    if (tid == 0) {
        g_bsum[blin] = sred[0];
        __threadfence();
        unsigned int ticket = atomicAdd(&g_count, 1u);
        s_last = (ticket == NBLK - 1) ? 1 : 0;
    }
    __syncthreads();

    if (s_last) {
        __threadfence();
        double v = (tid < NBLK) ? g_bsum[tid] : 0.0;
        sred[tid] = v;
        __syncthreads();
        // reduce within each 64-block group (part0: 0..63, part1: 64..127)
        for (int s = 32; s > 0; s >>= 1) {
            if (tid < NBLK && (tid & 63) < s) sred[tid] += sred[tid + s];
            __syncthreads();
        }
        if (tid == 0) {
            double obj0 = sred[0]  / (double)NPTS;
            double obj1 = sred[64] / (double)NPTS;
            out[1] = (float)obj0;
            out[2] = (float)obj1;
            out[0] = (float)(((double)pw[0] * obj0 + (double)pw[1] * obj1) / 2.0);
            g_count = 0;   // reset for next graph replay
        }
    }
}

// ---------------------------------------------------------------------------
extern "C" void kernel_launch(void* const* d_in, const int* in_sizes, int n_in,
                              void* d_out, int out_size)
{
    const float* cam  = (const float*)d_in[0];  // camera_pts [2,8192,3]
    const float* cad  = (const float*)d_in[1];  // cad_pts    [2,8192,3]
    const float* xyz  = (const float*)d_in[2];  // [1,3]
    const float* rpy  = (const float*)d_in[3];  // [1,3]
    const float* pw   = (const float*)d_in[4];  // [2]
    const float* quat = (const float*)d_in[5];  // [4]
    const float* bt   = (const float*)d_in[6];  // [3,1]
    const float* th   = (const float*)d_in[7];  // [1]
    float* out = (float*)d_out;

    dim3 grid(NPTS / TPB, 2, 2);   // 128 blocks, one wave, balanced
    k_fused<<<grid, TPB>>>(cam, cad, xyz, rpy, quat, bt, th, pw, out);
}